// round 9
// baseline (speedup 1.0000x reference)
#include <cuda_runtime.h>
#include <cuda_bf16.h>
#include <math.h>
#include <stdint.h>

#define Bsz 256
#define Slen 128
#define Fdim 128
#define Hdim 512
#define Cdim 64
#define Ldim 16
#define KTOT 640

#define ROWB 144                     // A smem row stride bytes
#define WROWB 1296                   // W smem row stride (640*2 + 16)
#define WHALF (64 * WROWB)           // 82944 per half
#define AHALF (64 * ROWB)            // 9216
#define ABUF  (2 * AHALF)            // 18432
#define AOFF  (2 * WHALF)            // 165888
#define BIASOFF (AOFF + 3 * ABUF)    // 221184
#define SMEM_TOTAL (BIASOFF + 256)   // 221440
#define CST 68

// -------- device globals --------
__device__ __align__(16) __nv_bfloat16 g_Wh[2048 * KTOT];
__device__ __align__(16) __nv_bfloat16 g_Wl[2048 * KTOT];
__device__ __align__(16) __nv_bfloat16 g_xh[Bsz * Slen * Fdim];
__device__ __align__(16) __nv_bfloat16 g_xl[Bsz * Slen * Fdim];
__device__ __align__(16) __nv_bfloat16 g_hh[2][Bsz * Hdim];
__device__ __align__(16) __nv_bfloat16 g_hl[2][Bsz * Hdim];
__device__ float g_c[Bsz * Hdim];
__device__ float g_ctx[Bsz * 3 * Hdim];
__device__ int g_cntA;
__device__ volatile int g_flgA;
__device__ int g_cntG[4];
__device__ volatile int g_flgG[4];

__device__ __forceinline__ uint32_t smem_u32(const void* p) {
    uint32_t a;
    asm("{ .reg .u64 t; cvta.to.shared.u64 t, %1; cvt.u32.u64 %0, t; }" : "=r"(a) : "l"(p));
    return a;
}
__device__ __forceinline__ void cp16(uint32_t sdst, const void* gsrc) {
    asm volatile("cp.async.cg.shared.global [%0], [%1], 16;" :: "r"(sdst), "l"(gsrc));
}
#define CP_COMMIT() asm volatile("cp.async.commit_group;" ::: "memory")
#define CP_WAIT(n)  asm volatile("cp.async.wait_group %0;" :: "n"(n) : "memory")

__device__ __forceinline__ void ldsm_x4(uint32_t addr, uint32_t r[4]) {
    asm volatile("ldmatrix.sync.aligned.m8n8.x4.shared.b16 {%0,%1,%2,%3}, [%4];"
                 : "=r"(r[0]), "=r"(r[1]), "=r"(r[2]), "=r"(r[3]) : "r"(addr));
}
__device__ __forceinline__ void mma16816(float c[4], const uint32_t a[4], const uint32_t b[2]) {
    asm volatile(
        "mma.sync.aligned.m16n8k16.row.col.f32.bf16.bf16.f32 "
        "{%0,%1,%2,%3}, {%4,%5,%6,%7}, {%8,%9}, {%0,%1,%2,%3};"
        : "+f"(c[0]), "+f"(c[1]), "+f"(c[2]), "+f"(c[3])
        : "r"(a[0]), "r"(a[1]), "r"(a[2]), "r"(a[3]), "r"(b[0]), "r"(b[1]));
}
__device__ __forceinline__ float sigf(float x) {
    return __fdividef(1.0f, 1.0f + __expf(-x));
}
__device__ __forceinline__ float tanh_fast(float x) {
    float xc = fminf(fmaxf(x, -15.0f), 15.0f);
    float e = __expf(2.0f * xc);
    return __fdividef(e - 1.0f, e + 1.0f);
}

// ---------------------------------------------------------------------------
// ONE persistent kernel. grid (32,4) = 128 CTAs, 256 threads.
// Warps: wm = wid&1 (M32), wn = (wid>>1)&1 (N32), wk = wid>>2 (K32 split).
// ---------------------------------------------------------------------------
__global__ __launch_bounds__(256) void vae_persist(
    const float* __restrict__ x, const float* __restrict__ context,
    const float* __restrict__ eps,
    const float* __restrict__ W_ih, const float* __restrict__ b_ih,
    const float* __restrict__ W_hh, const float* __restrict__ b_hh,
    const float* __restrict__ cg_w1, const float* __restrict__ cg_b1,
    const float* __restrict__ cg_w2, const float* __restrict__ cg_b2,
    const float* __restrict__ mu_w, const float* __restrict__ mu_b,
    const float* __restrict__ lv_w, const float* __restrict__ lv_b,
    const float* __restrict__ dec_w1, const float* __restrict__ dec_b1,
    const float* __restrict__ dec_w2, const float* __restrict__ dec_b2,
    float* __restrict__ out)
{
    extern __shared__ char smem[];
    const uint32_t sb = smem_u32(smem);
    const int tid = threadIdx.x;
    const int wid = tid >> 5, lane = tid & 31;
    const int wm = wid & 1, wn = (wid >> 1) & 1, wk = wid >> 2;
    const int gID = lane >> 2, tid4 = lane & 3;
    const int bx = blockIdx.x, by = blockIdx.y;
    const int rank = by * 32 + bx;
    const int n0 = bx * 64, hcol0 = bx * 16, b0 = by * 64;

    __shared__ int s_baseA, s_baseG;
    if (tid == 0) { s_baseA = g_flgA; s_baseG = g_flgG[by]; }
    __syncthreads();
    const int baseA = s_baseA, baseG = s_baseG;

    auto gbarA = [&](int target) {
        __syncthreads();
        if (tid == 0) {
            __threadfence();
            if (atomicAdd(&g_cntA, 1) == 127) {
                atomicExch(&g_cntA, 0);
                __threadfence();
                g_flgA = target;
            } else {
                while (g_flgA < target) { }
            }
            __threadfence();
        }
        __syncthreads();
    };

    // ================= Phase A: prep =======================================
#pragma unroll
    for (int i = 0; i < 4; i++) {
        int idx = rank * 1024 + i * 256 + tid;
        g_c[idx] = 0.0f;
        g_hh[0][idx] = __float2bfloat16(0.0f);
        g_hl[0][idx] = __float2bfloat16(0.0f);
    }
    for (int i = 0; i < 40; i++) {
        int idx = rank * 10240 + i * 256 + tid;
        int np = idx / KTOT, k = idx - np * KTOT;
        int n = (np & 3) * Hdim + (np >> 2);
        float v = (k < Hdim) ? W_hh[k * 2048 + n] : W_ih[(k - Hdim) * 2048 + n];
        __nv_bfloat16 hi = __float2bfloat16(v);
        g_Wh[idx] = hi;
        g_Wl[idx] = __float2bfloat16(v - __bfloat162float(hi));
    }
    for (int i = 0; i < 128; i++) {
        int idx = rank * 32768 + i * 256 + tid;
        float v = x[idx];
        __nv_bfloat16 hi = __float2bfloat16(v);
        g_xh[idx] = hi;
        g_xl[idx] = __float2bfloat16(v - __bfloat162float(hi));
    }
    {
        float* ctxrow = (float*)smem;
        float* tmp = (float*)(smem + 1024);
        if (tid < 128) {
            int row = tid >> 6, k = tid & 63;
            ctxrow[row * 64 + k] = context[(rank * 2 + row) * Cdim + k];
        }
        __syncthreads();
#pragma unroll
        for (int i = 0; i < 4; i++) {
            int idx = i * 256 + tid;
            int row = idx >> 9, n = idx & 511;
            float s = cg_b1[n];
            for (int k = 0; k < Cdim; k++) s += ctxrow[row * 64 + k] * cg_w1[k * Hdim + n];
            tmp[row * 512 + n] = fmaxf(s, 0.0f);
        }
        __syncthreads();
        for (int i = 0; i < 12; i++) {
            int idx = i * 256 + tid;
            int row = idx / 1536, n = idx - row * 1536;
            float s = cg_b2[n];
            const float* tr = tmp + row * 512;
            for (int k = 0; k < Hdim; k++) s += tr[k] * cg_w2[k * 1536 + n];
            g_ctx[(rank * 2 + row) * 1536 + n] = 1.0f / (1.0f + expf(-s));
        }
    }
    gbarA(baseA + 1);

    // ================= Phase B: W tile -> smem =============================
    if (tid < 64) {
        int np = n0 + tid;
        int n = (np & 3) * Hdim + (np >> 2);
        ((float*)(smem + BIASOFF))[tid] = b_ih[n] + b_hh[n];
    }
    for (int i = 0; i < 40; i++) {
        int j = i * 256 + tid;
        int half = j / 5120, rem = j - half * 5120;
        int row = rem / 80, q = rem - row * 80;
        cp16(sb + half * WHALF + row * WROWB + q * 16,
             (half ? g_Wl : g_Wh) + (size_t)(n0 + row) * KTOT + q * 8);
    }
    CP_COMMIT();

    // ================= LSTM steps ==========================================
    float acc[2][4][4];

    // per-warp ldmatrix lane addresses (A: row-major m x k; B: [n][k])
    const uint32_t aBase0 = sb + AOFF
        + (uint32_t)(wm * 32 + (lane & 15)) * ROWB
        + (uint32_t)(wk * 64 + ((lane >> 4) * 16));
    const uint32_t bBase0 = sb
        + (uint32_t)(wn * 32 + ((lane >> 4) & 1) * 8 + (lane & 7)) * WROWB
        + (uint32_t)(wk * 64 + (((lane >> 3) & 1) * 16));

    auto copyA = [&](int s, int t,
                     const __nv_bfloat16* hh, const __nv_bfloat16* hl) {
        const int kc = (s < 2) ? 8 + s : s - 2;
        const uint32_t abase = sb + AOFF + (uint32_t)(s % 3) * ABUF;
#pragma unroll
        for (int half = 0; half < 2; half++) {
#pragma unroll
            for (int i = 0; i < 2; i++) {
                int idx = i * 256 + tid, r = idx >> 3, q = idx & 7;
                uint32_t dst = abase + half * AHALF + r * ROWB + q * 16;
                if (kc < 8) {
                    const __nv_bfloat16* src = half ? hl : hh;
                    cp16(dst, src + (size_t)(b0 + r) * Hdim + kc * 64 + q * 8);
                } else {
                    const __nv_bfloat16* src = half ? g_xl : g_xh;
                    cp16(dst, src + ((size_t)(b0 + r) * Slen + t) * Fdim + (kc - 8) * 64 + q * 8);
                }
            }
        }
    };

    auto compute = [&](int s) {
        const int kc = (s < 2) ? 8 + s : s - 2;
        const uint32_t abuf = aBase0 + (uint32_t)(s % 3) * ABUF;
        const uint32_t bbuf = bBase0 + (uint32_t)kc * 128;
#pragma unroll
        for (int ks = 0; ks < 2; ks++) {
            uint32_t aH[2][4], aL[2][4];
#pragma unroll
            for (int mi = 0; mi < 2; mi++) {
                ldsm_x4(abuf + mi * (16 * ROWB) + ks * 32, aH[mi]);
                ldsm_x4(abuf + mi * (16 * ROWB) + ks * 32 + AHALF, aL[mi]);
            }
#pragma unroll
            for (int nj = 0; nj < 2; nj++) {
                uint32_t bH[4], bL[4];
                ldsm_x4(bbuf + nj * (16 * WROWB) + ks * 32, bH);
                ldsm_x4(bbuf + nj * (16 * WROWB) + ks * 32 + WHALF, bL);
#pragma unroll
                for (int mi = 0; mi < 2; mi++) {
                    mma16816(acc[mi][nj * 2 + 0], aH[mi], bH + 0);
                    mma16816(acc[mi][nj * 2 + 0], aH[mi], bL + 0);
                    mma16816(acc[mi][nj * 2 + 0], aL[mi], bH + 0);
                    mma16816(acc[mi][nj * 2 + 1], aH[mi], bH + 2);
                    mma16816(acc[mi][nj * 2 + 1], aH[mi], bL + 2);
                    mma16816(acc[mi][nj * 2 + 1], aL[mi], bH + 2);
                }
            }
        }
    };

    for (int t = 0; t < Slen; t++) {
        const __nv_bfloat16* hh = g_hh[t & 1];
        const __nv_bfloat16* hl = g_hl[t & 1];
        __nv_bfloat16* ohh = g_hh[(t + 1) & 1];
        __nv_bfloat16* ohl = g_hl[(t + 1) & 1];

#pragma unroll
        for (int mi = 0; mi < 2; mi++)
#pragma unroll
            for (int j = 0; j < 4; j++)
#pragma unroll
                for (int r = 0; r < 4; r++) acc[mi][j][r] = 0.0f;

        // x chunks: prefetch + compute BEFORE the wait (no h dependency)
        copyA(0, t, hh, hl); CP_COMMIT();
        copyA(1, t, hh, hl); CP_COMMIT();
        CP_WAIT(1); __syncthreads(); compute(0);
        CP_WAIT(0); __syncthreads(); compute(1);

        // wait: previous step's h published by the whole by-group
        if (t > 0) {
            if (tid == 0) {
                const int target = baseG + t;
                while (g_flgG[by] < target) { }
                __threadfence();
            }
            __syncthreads();
        }

        copyA(2, t, hh, hl); CP_COMMIT();
        copyA(3, t, hh, hl); CP_COMMIT();
        copyA(4, t, hh, hl); CP_COMMIT();
#pragma unroll 1
        for (int i = 0; i < 8; i++) {
            if (i <= 5)      { CP_WAIT(2); }
            else if (i == 6) { CP_WAIT(1); }
            else             { CP_WAIT(0); }
            __syncthreads();
            compute(i + 2);
            __syncthreads();
            if (i + 5 <= 9) { copyA(i + 5, t, hh, hl); CP_COMMIT(); }
        }

        // ---- epilogue: cross-k reduce in smem, fused LSTM update ----
        float* Csm = (float*)(smem + AOFF);
        if (wk == 0) {
#pragma unroll
            for (int mi = 0; mi < 2; mi++)
#pragma unroll
                for (int j = 0; j < 4; j++) {
                    int row = wm * 32 + mi * 16 + gID;
                    int col = wn * 32 + (j >> 1) * 16 + (j & 1) * 8 + tid4 * 2;
                    *(float2*)&Csm[row * CST + col] = make_float2(acc[mi][j][0], acc[mi][j][1]);
                    *(float2*)&Csm[(row + 8) * CST + col] = make_float2(acc[mi][j][2], acc[mi][j][3]);
                }
        }
        __syncthreads();
        if (wk == 1) {
#pragma unroll
            for (int mi = 0; mi < 2; mi++)
#pragma unroll
                for (int j = 0; j < 4; j++) {
                    int row = wm * 32 + mi * 16 + gID;
                    int col = wn * 32 + (j >> 1) * 16 + (j & 1) * 8 + tid4 * 2;
                    float2 v0 = *(float2*)&Csm[row * CST + col];
                    v0.x += acc[mi][j][0]; v0.y += acc[mi][j][1];
                    *(float2*)&Csm[row * CST + col] = v0;
                    float2 v1 = *(float2*)&Csm[(row + 8) * CST + col];
                    v1.x += acc[mi][j][2]; v1.y += acc[mi][j][3];
                    *(float2*)&Csm[(row + 8) * CST + col] = v1;
                }
        }
        __syncthreads();
        const float* bias = (const float*)(smem + BIASOFF);
#pragma unroll
        for (int it = 0; it < 4; it++) {
            int idx = it * 256 + tid;
            int m = idx >> 4, hcl = idx & 15;
            float4 gv = *(float4*)&Csm[m * CST + hcl * 4];
            float4 bb = *(const float4*)&bias[hcl * 4];
            int b = b0 + m, hc = hcol0 + hcl;
            const float* cxp = g_ctx + (size_t)b * 1536;
            float iv = sigf(gv.x + bb.x) * cxp[hc];
            float fv = sigf(gv.y + bb.y) * cxp[Hdim + hc];
            float gg = tanh_fast(gv.z + bb.z);
            float ov = sigf(gv.w + bb.w) * cxp[2 * Hdim + hc];
            float cn = fv * g_c[(size_t)b * Hdim + hc] + iv * gg;
            g_c[(size_t)b * Hdim + hc] = cn;
            float hv = ov * tanh_fast(cn);
            __nv_bfloat16 hhi = __float2bfloat16(hv);
            ohh[(size_t)b * Hdim + hc] = hhi;
            ohl[(size_t)b * Hdim + hc] = __float2bfloat16(hv - __bfloat162float(hhi));
        }
        __syncthreads();
        // arrive: publish h for epoch t+1 (group-scope)
        if (tid == 0) {
            __threadfence();
            if (atomicAdd(&g_cntG[by], 1) == 31) {
                atomicExch(&g_cntG[by], 0);
                __threadfence();
                g_flgG[by] = baseG + t + 1;
            }
        }
    }

    gbarA(baseA + 2);   // final h globally visible

    // ================= VAE head: rows 2*rank, 2*rank+1 =====================
    {
        float* hrow = (float*)smem;
        float* zv   = (float*)(smem + 4096);
        float* d1   = (float*)(smem + 4352);
#pragma unroll
        for (int i = 0; i < 4; i++) {
            int idx = i * 256 + tid;
            int row = idx >> 9, k = idx & 511;
            int b = rank * 2 + row;
            hrow[idx] = __bfloat162float(g_hh[0][(size_t)b * Hdim + k]) +
                        __bfloat162float(g_hl[0][(size_t)b * Hdim + k]);
        }
        __syncthreads();
        if (tid < 32) {
            int row = tid >> 4, j = tid & 15;
            int b = rank * 2 + row;
            const float* hr = hrow + row * 512;
            float m = mu_b[j];
            for (int k = 0; k < Hdim; k++) m += hr[k] * mu_w[k * Ldim + j];
            float lv = lv_b[j];
            for (int k = 0; k < Hdim; k++) lv += hr[k] * lv_w[k * Ldim + j];
            out[Bsz * Fdim + b * Ldim + j] = m;
            out[Bsz * Fdim + Bsz * Ldim + b * Ldim + j] = lv;
            zv[tid] = m + eps[b * Ldim + j] * expf(0.5f * lv);
        }
        __syncthreads();
#pragma unroll
        for (int i = 0; i < 4; i++) {
            int idx = i * 256 + tid;
            int row = idx >> 9, n = idx & 511;
            float s = dec_b1[n];
            const float* z = zv + row * 16;
#pragma unroll
            for (int k = 0; k < Ldim; k++) s += z[k] * dec_w1[k * Hdim + n];
            d1[idx] = fmaxf(s, 0.0f);
        }
        __syncthreads();
        {
            int row = tid >> 7, n = tid & 127;
            int b = rank * 2 + row;
            float s = dec_b2[n];
            const float* dr = d1 + row * 512;
            for (int k = 0; k < Hdim; k++) s += dr[k] * dec_w2[k * Fdim + n];
            out[(size_t)b * Fdim + n] = s;
        }
    }
}

// ---------------------------------------------------------------------------
extern "C" void kernel_launch(void* const* d_in, const int* in_sizes, int n_in,
                              void* d_out, int out_size)
{
    const float* x       = (const float*)d_in[0];
    const float* context = (const float*)d_in[1];
    const float* eps     = (const float*)d_in[2];
    const float* W_ih    = (const float*)d_in[3];
    const float* b_ih    = (const float*)d_in[4];
    const float* W_hh    = (const float*)d_in[5];
    const float* b_hh    = (const float*)d_in[6];
    const float* cg_w1   = (const float*)d_in[7];
    const float* cg_b1   = (const float*)d_in[8];
    const float* cg_w2   = (const float*)d_in[9];
    const float* cg_b2   = (const float*)d_in[10];
    const float* mu_w    = (const float*)d_in[11];
    const float* mu_b    = (const float*)d_in[12];
    const float* lv_w    = (const float*)d_in[13];
    const float* lv_b    = (const float*)d_in[14];
    const float* dec_w1  = (const float*)d_in[15];
    const float* dec_b1  = (const float*)d_in[16];
    const float* dec_w2  = (const float*)d_in[17];
    const float* dec_b2  = (const float*)d_in[18];
    float* out = (float*)d_out;

    cudaFuncSetAttribute(vae_persist, cudaFuncAttributeMaxDynamicSharedMemorySize,
                         SMEM_TOTAL);

    vae_persist<<<dim3(32, 4), 256, SMEM_TOTAL>>>(
        x, context, eps, W_ih, b_ih, W_hh, b_hh,
        cg_w1, cg_b1, cg_w2, cg_b2, mu_w, mu_b, lv_w, lv_b,
        dec_w1, dec_b1, dec_w2, dec_b2, out);
}

// round 10
// speedup vs baseline: 1.0616x; 1.0616x over previous
#include <cuda_runtime.h>
#include <cuda_bf16.h>
#include <math.h>
#include <stdint.h>

#define Bsz 256
#define Slen 128
#define Fdim 128
#define Hdim 512
#define Cdim 64
#define Ldim 16
#define KTOT 640
#define G4 2048

// step: CTA = M32 x N64, K=512 in 8 chunks of 64
#define NCHS 8
#define ROWB 144
#define AHALF (32 * ROWB)            // 4608
#define WCH   (64 * ROWB)            // 9216
#define BUFB  (2 * AHALF + 2 * WCH)  // 27648
#define BIASOFF (3 * BUFB)           // 82944
#define SMEM_STEP (BIASOFF + 256)    // 83200
#define CST 68

// -------- device globals --------
__device__ __align__(16) __nv_bfloat16 g_Wh[G4 * KTOT];
__device__ __align__(16) __nv_bfloat16 g_Wl[G4 * KTOT];
__device__ __align__(16) __nv_bfloat16 g_xh[Bsz * Slen * Fdim];
__device__ __align__(16) __nv_bfloat16 g_xl[Bsz * Slen * Fdim];
__device__ __align__(16) __nv_bfloat16 g_hh[2][Bsz * Hdim];
__device__ __align__(16) __nv_bfloat16 g_hl[2][Bsz * Hdim];
__device__ float g_c[Bsz * Hdim];
__device__ float g_ctx[Bsz * 3 * Hdim];
__device__ __align__(16) float g_xg[(size_t)Slen * Bsz * G4];   // precomputed x@W_ih (no bias)

__device__ __forceinline__ uint32_t smem_u32(const void* p) {
    uint32_t a;
    asm("{ .reg .u64 t; cvta.to.shared.u64 t, %1; cvt.u32.u64 %0, t; }" : "=r"(a) : "l"(p));
    return a;
}
__device__ __forceinline__ void cp16(uint32_t sdst, const void* gsrc) {
    asm volatile("cp.async.cg.shared.global [%0], [%1], 16;" :: "r"(sdst), "l"(gsrc));
}
#define CP_COMMIT() asm volatile("cp.async.commit_group;" ::: "memory")
#define CP_WAIT(n)  asm volatile("cp.async.wait_group %0;" :: "n"(n) : "memory")

__device__ __forceinline__ void mma16816(float c[4], const uint32_t a[4], const uint32_t b[2]) {
    asm volatile(
        "mma.sync.aligned.m16n8k16.row.col.f32.bf16.bf16.f32 "
        "{%0,%1,%2,%3}, {%4,%5,%6,%7}, {%8,%9}, {%0,%1,%2,%3};"
        : "+f"(c[0]), "+f"(c[1]), "+f"(c[2]), "+f"(c[3])
        : "r"(a[0]), "r"(a[1]), "r"(a[2]), "r"(a[3]), "r"(b[0]), "r"(b[1]));
}
__device__ __forceinline__ float sigf(float x) {
    return __fdividef(1.0f, 1.0f + __expf(-x));
}
__device__ __forceinline__ float tanh_fast(float x) {
    float xc = fminf(fmaxf(x, -15.0f), 15.0f);
    float e = __expf(2.0f * xc);
    return __fdividef(e - 1.0f, e + 1.0f);
}

// fragment loads shared by both GEMM kernels (A: 32 rows; W: 64 rows; [row][k] 144B rows)
__device__ __forceinline__ void lda_frag(const char* Abuf, int wm, int gID, int kb,
                                         uint32_t ah[4], uint32_t al[4]) {
    const char* ar = Abuf + (wm * 16 + gID) * ROWB + kb;
    ah[0] = *(const uint32_t*)(ar);
    ah[2] = *(const uint32_t*)(ar + 16);
    ah[1] = *(const uint32_t*)(ar + 8 * ROWB);
    ah[3] = *(const uint32_t*)(ar + 8 * ROWB + 16);
    const char* arl = ar + AHALF;
    al[0] = *(const uint32_t*)(arl);
    al[2] = *(const uint32_t*)(arl + 16);
    al[1] = *(const uint32_t*)(arl + 8 * ROWB);
    al[3] = *(const uint32_t*)(arl + 8 * ROWB + 16);
}

// ------------------------- prep kernels -------------------------
__global__ __launch_bounds__(256) void zero_state_kernel() {
    int i = blockIdx.x * 256 + threadIdx.x;
    if (i < Bsz * Hdim) {
        g_c[i] = 0.0f;
        g_hh[0][i] = __float2bfloat16(0.0f);
        g_hl[0][i] = __float2bfloat16(0.0f);
    }
}
__global__ __launch_bounds__(256) void split_w_kernel(
    const float* __restrict__ W_ih, const float* __restrict__ W_hh)
{
    int idx = blockIdx.x * 256 + threadIdx.x;
    if (idx >= G4 * KTOT) return;
    int np = idx / KTOT, k = idx - np * KTOT;
    int n = (np & 3) * Hdim + (np >> 2);
    float v = (k < Hdim) ? W_hh[k * G4 + n] : W_ih[(k - Hdim) * G4 + n];
    __nv_bfloat16 hi = __float2bfloat16(v);
    g_Wh[idx] = hi;
    g_Wl[idx] = __float2bfloat16(v - __bfloat162float(hi));
}
__global__ __launch_bounds__(256) void split_x_kernel(const float* __restrict__ x) {
    int i = blockIdx.x * 256 + threadIdx.x;
    if (i >= Bsz * Slen * Fdim) return;
    float v = x[i];
    __nv_bfloat16 hi = __float2bfloat16(v);
    g_xh[i] = hi;
    g_xl[i] = __float2bfloat16(v - __bfloat162float(hi));
}
__global__ __launch_bounds__(128) void ctx1_kernel(
    const float* __restrict__ context, const float* __restrict__ cg_w1,
    const float* __restrict__ cg_b1, float* __restrict__ tmp_out)
{
    __shared__ float cr[Cdim];
    int b = blockIdx.x;
    for (int k = threadIdx.x; k < Cdim; k += 128) cr[k] = context[b * Cdim + k];
    __syncthreads();
#pragma unroll
    for (int j = 0; j < 4; j++) {
        int n = threadIdx.x + j * 128;
        float s = cg_b1[n];
        for (int k = 0; k < Cdim; k++) s += cr[k] * cg_w1[k * Hdim + n];
        tmp_out[b * Hdim + n] = fmaxf(s, 0.0f);
    }
}
__device__ float g_tmp[Bsz * Hdim];
__global__ __launch_bounds__(256) void ctx2_kernel(
    const float* __restrict__ cg_w2, const float* __restrict__ cg_b2)
{
    __shared__ float tr[Hdim];
    int b = blockIdx.x;
    for (int k = threadIdx.x; k < Hdim; k += 256) tr[k] = g_tmp[b * Hdim + k];
    __syncthreads();
#pragma unroll
    for (int j = 0; j < 6; j++) {
        int n = threadIdx.x + j * 256;
        float s = cg_b2[n];
        for (int k = 0; k < Hdim; k++) s += tr[k] * cg_w2[k * 3 * Hdim + n];
        g_ctx[b * 3 * Hdim + n] = 1.0f / (1.0f + expf(-s));
    }
}

// ------------------- xg precompute GEMM -------------------
// grid (32, 1024): bx = n-tile (64 cols), by = m-tile (32 rows of t*256+b).
// K = 128 (W cols 512..639), 2 chunks. Output raw fp32 (no bias).
__global__ __launch_bounds__(256) void xgemm_kernel()
{
    extern __shared__ char smem[];
    const uint32_t sb = smem_u32(smem);
    const int tid = threadIdx.x;
    const int wid = tid >> 5, lane = tid & 31;
    const int wm = wid & 1, wn = wid >> 1;
    const int gID = lane >> 2, tid4 = lane & 3;
    const int n0 = blockIdx.x * 64;
    const int m0 = blockIdx.y * 32;
    const int t = m0 >> 8, brow0 = m0 & 255;

    float acc[2][4];
#pragma unroll
    for (int nj = 0; nj < 2; nj++)
#pragma unroll
        for (int r = 0; r < 4; r++) acc[nj][r] = 0.0f;

    auto copyc = [&](int c) {
        const uint32_t base = sb + (uint32_t)c * BUFB;
#pragma unroll
        for (int i = 0; i < 2; i++) {
            int idx = i * 256 + tid;
            int half = idx >> 8, rem = idx & 255, r = rem >> 3, q = rem & 7;
            cp16(base + half * AHALF + r * ROWB + q * 16,
                 (half ? g_xl : g_xh) + ((size_t)(brow0 + r) * Slen + t) * Fdim + c * 64 + q * 8);
        }
#pragma unroll
        for (int i = 0; i < 4; i++) {
            int idx = i * 256 + tid;
            int half = idx >> 9, rem = idx & 511, r = rem >> 3, q = rem & 7;
            cp16(base + 2 * AHALF + half * WCH + r * ROWB + q * 16,
                 (half ? g_Wl : g_Wh) + (size_t)(n0 + r) * KTOT + (8 + c) * 64 + q * 8);
        }
    };
    auto computec = [&](int c) {
        const char* base = smem + (size_t)c * BUFB;
        const char* Bb = base + 2 * AHALF;
#pragma unroll
        for (int ks = 0; ks < 4; ks++) {
            const int kb = ks * 32 + tid4 * 4;
            uint32_t ah[4], al[4];
            lda_frag(base, wm, gID, kb, ah, al);
#pragma unroll
            for (int nj = 0; nj < 2; nj++) {
                const char* br = Bb + (wn * 16 + nj * 8 + gID) * ROWB + kb;
                uint32_t bh[2], bl[2];
                bh[0] = *(const uint32_t*)(br);
                bh[1] = *(const uint32_t*)(br + 16);
                bl[0] = *(const uint32_t*)(br + WCH);
                bl[1] = *(const uint32_t*)(br + WCH + 16);
                mma16816(acc[nj], ah, bh);
                mma16816(acc[nj], ah, bl);
                mma16816(acc[nj], al, bh);
            }
        }
    };

    copyc(0); CP_COMMIT();
    copyc(1); CP_COMMIT();
    CP_WAIT(1); __syncthreads(); computec(0);
    CP_WAIT(0); __syncthreads(); computec(1);

    const int row = wm * 16 + gID;
#pragma unroll
    for (int nj = 0; nj < 2; nj++) {
        int col = n0 + wn * 16 + nj * 8 + tid4 * 2;
        *(float2*)&g_xg[(size_t)(m0 + row) * G4 + col] = make_float2(acc[nj][0], acc[nj][1]);
        *(float2*)&g_xg[(size_t)(m0 + row + 8) * G4 + col] = make_float2(acc[nj][2], acc[nj][3]);
    }
}

// ------------------- LSTM step kernel -------------------
// grid (32, 8) = 256 CTAs (2/SM). CTA = M32 batch x N64 gate-cols, K=512.
// acc initialized from precomputed xg; fused LSTM epilogue.
__global__ __launch_bounds__(256) void step_kernel(
    const float* __restrict__ b_ih, const float* __restrict__ b_hh, int t)
{
    extern __shared__ char smem[];
    const uint32_t sb = smem_u32(smem);
    const int tid = threadIdx.x;
    const int wid = tid >> 5, lane = tid & 31;
    const int wm = wid & 1, wn = wid >> 1;
    const int gID = lane >> 2, tid4 = lane & 3;
    const int n0 = blockIdx.x * 64;
    const int hcol0 = blockIdx.x * 16;
    const int b0 = blockIdx.y * 32;

    const __nv_bfloat16* __restrict__ hh = g_hh[t & 1];
    const __nv_bfloat16* __restrict__ hl = g_hl[t & 1];
    __nv_bfloat16* __restrict__ ohh = g_hh[(t + 1) & 1];
    __nv_bfloat16* __restrict__ ohl = g_hl[(t + 1) & 1];

    if (tid < 64) {
        int np = n0 + tid;
        int n = (np & 3) * Hdim + (np >> 2);
        ((float*)(smem + BIASOFF))[tid] = b_ih[n] + b_hh[n];
    }

    // init accumulators from precomputed x@W_ih
    float acc[2][4];
    {
        const int row = wm * 16 + gID;
        const size_t mrow = (size_t)(t * Bsz + b0 + row);
#pragma unroll
        for (int nj = 0; nj < 2; nj++) {
            int col = n0 + wn * 16 + nj * 8 + tid4 * 2;
            float2 v0 = *(const float2*)&g_xg[mrow * G4 + col];
            float2 v1 = *(const float2*)&g_xg[(mrow + 8) * G4 + col];
            acc[nj][0] = v0.x; acc[nj][1] = v0.y;
            acc[nj][2] = v1.x; acc[nj][3] = v1.y;
        }
    }

    auto copyc = [&](int c) {
        const int kc = c;
        const uint32_t base = sb + (uint32_t)(c % 3) * BUFB;
#pragma unroll
        for (int i = 0; i < 2; i++) {
            int idx = i * 256 + tid;
            int half = idx >> 8, rem = idx & 255, r = rem >> 3, q = rem & 7;
            cp16(base + half * AHALF + r * ROWB + q * 16,
                 (half ? hl : hh) + (size_t)(b0 + r) * Hdim + kc * 64 + q * 8);
        }
#pragma unroll
        for (int i = 0; i < 4; i++) {
            int idx = i * 256 + tid;
            int half = idx >> 9, rem = idx & 511, r = rem >> 3, q = rem & 7;
            cp16(base + 2 * AHALF + half * WCH + r * ROWB + q * 16,
                 (half ? g_Wl : g_Wh) + (size_t)(n0 + r) * KTOT + kc * 64 + q * 8);
        }
    };
    auto computec = [&](int c) {
        const char* base = smem + (size_t)(c % 3) * BUFB;
        const char* Bb = base + 2 * AHALF;
#pragma unroll
        for (int ks = 0; ks < 4; ks++) {
            const int kb = ks * 32 + tid4 * 4;
            uint32_t ah[4], al[4];
            lda_frag(base, wm, gID, kb, ah, al);
#pragma unroll
            for (int nj = 0; nj < 2; nj++) {
                const char* br = Bb + (wn * 16 + nj * 8 + gID) * ROWB + kb;
                uint32_t bh[2], bl[2];
                bh[0] = *(const uint32_t*)(br);
                bh[1] = *(const uint32_t*)(br + 16);
                bl[0] = *(const uint32_t*)(br + WCH);
                bl[1] = *(const uint32_t*)(br + WCH + 16);
                mma16816(acc[nj], ah, bh);
                mma16816(acc[nj], ah, bl);
                mma16816(acc[nj], al, bh);
            }
        }
    };

    copyc(0); CP_COMMIT();
    copyc(1); CP_COMMIT();
#pragma unroll 1
    for (int c = 0; c < NCHS; c++) {
        if (c + 2 < NCHS) { copyc(c + 2); CP_COMMIT(); }
        if (c + 2 < NCHS)      { CP_WAIT(2); }
        else if (c + 1 < NCHS) { CP_WAIT(1); }
        else                   { CP_WAIT(0); }
        __syncthreads();
        computec(c);
        __syncthreads();
    }

    // ---- epilogue: acc -> Csm -> fused LSTM update ----
    float* Csm = (float*)smem;   // 32 x CST (overlays buffer 0; safe after last sync)
    {
        const int row = wm * 16 + gID;
#pragma unroll
        for (int nj = 0; nj < 2; nj++) {
            int col = wn * 16 + nj * 8 + tid4 * 2;
            *(float2*)&Csm[row * CST + col] = make_float2(acc[nj][0], acc[nj][1]);
            *(float2*)&Csm[(row + 8) * CST + col] = make_float2(acc[nj][2], acc[nj][3]);
        }
    }
    __syncthreads();
    const float* bias = (const float*)(smem + BIASOFF);
#pragma unroll
    for (int it = 0; it < 2; it++) {
        int idx = it * 256 + tid;
        int m = idx >> 4, hcl = idx & 15;
        float4 gv = *(float4*)&Csm[m * CST + hcl * 4];
        float4 bb = *(const float4*)&bias[hcl * 4];
        int b = b0 + m, hc = hcol0 + hcl;
        const float* cxp = g_ctx + (size_t)b * 1536;
        float iv = sigf(gv.x + bb.x) * cxp[hc];
        float fv = sigf(gv.y + bb.y) * cxp[Hdim + hc];
        float gg = tanh_fast(gv.z + bb.z);
        float ov = sigf(gv.w + bb.w) * cxp[2 * Hdim + hc];
        float cn = fv * g_c[(size_t)b * Hdim + hc] + iv * gg;
        g_c[(size_t)b * Hdim + hc] = cn;
        float hv = ov * tanh_fast(cn);
        __nv_bfloat16 hhi = __float2bfloat16(hv);
        ohh[(size_t)b * Hdim + hc] = hhi;
        ohl[(size_t)b * Hdim + hc] = __float2bfloat16(hv - __bfloat162float(hhi));
    }
}

// ------------------------- VAE head -------------------------
__global__ __launch_bounds__(128) void head_kernel(
    const float* __restrict__ eps,
    const float* __restrict__ mu_w, const float* __restrict__ mu_b,
    const float* __restrict__ lv_w, const float* __restrict__ lv_b,
    const float* __restrict__ dec_w1, const float* __restrict__ dec_b1,
    const float* __restrict__ dec_w2, const float* __restrict__ dec_b2,
    float* __restrict__ out)
{
    __shared__ float hrow[Hdim];
    __shared__ float zv[Ldim];
    __shared__ float d1[Hdim];
    int b = blockIdx.x;

    for (int k = threadIdx.x; k < Hdim; k += 128)
        hrow[k] = __bfloat162float(g_hh[0][(size_t)b * Hdim + k]) +
                  __bfloat162float(g_hl[0][(size_t)b * Hdim + k]);
    __syncthreads();

    if (threadIdx.x < Ldim) {
        int j = threadIdx.x;
        float m = mu_b[j];
        for (int k = 0; k < Hdim; k++) m += hrow[k] * mu_w[k * Ldim + j];
        out[Bsz * Fdim + b * Ldim + j] = m;
        float lv = lv_b[j];
        for (int k = 0; k < Hdim; k++) lv += hrow[k] * lv_w[k * Ldim + j];
        out[Bsz * Fdim + Bsz * Ldim + b * Ldim + j] = lv;
        zv[j] = m + eps[b * Ldim + j] * expf(0.5f * lv);
    }
    __syncthreads();

    for (int n = threadIdx.x; n < Hdim; n += 128) {
        float s = dec_b1[n];
#pragma unroll
        for (int k = 0; k < Ldim; k++) s += zv[k] * dec_w1[k * Hdim + n];
        d1[n] = fmaxf(s, 0.0f);
    }
    __syncthreads();
    {
        int n = threadIdx.x;
        float s = dec_b2[n];
        for (int k = 0; k < Hdim; k++) s += d1[k] * dec_w2[k * Fdim + n];
        out[(size_t)b * Fdim + n] = s;
    }
}

// ---------------------------------------------------------------------------
extern "C" void kernel_launch(void* const* d_in, const int* in_sizes, int n_in,
                              void* d_out, int out_size)
{
    const float* x       = (const float*)d_in[0];
    const float* context = (const float*)d_in[1];
    const float* eps     = (const float*)d_in[2];
    const float* W_ih    = (const float*)d_in[3];
    const float* b_ih    = (const float*)d_in[4];
    const float* W_hh    = (const float*)d_in[5];
    const float* b_hh    = (const float*)d_in[6];
    const float* cg_w1   = (const float*)d_in[7];
    const float* cg_b1   = (const float*)d_in[8];
    const float* cg_w2   = (const float*)d_in[9];
    const float* cg_b2   = (const float*)d_in[10];
    const float* mu_w    = (const float*)d_in[11];
    const float* mu_b    = (const float*)d_in[12];
    const float* lv_w    = (const float*)d_in[13];
    const float* lv_b    = (const float*)d_in[14];
    const float* dec_w1  = (const float*)d_in[15];
    const float* dec_b1  = (const float*)d_in[16];
    const float* dec_w2  = (const float*)d_in[17];
    const float* dec_b2  = (const float*)d_in[18];
    float* out = (float*)d_out;

    static float* tmp_ptr = nullptr;
    // g_tmp address fetched implicitly by ctx1 via symbol is not allowed from host;
    // ctx1 writes through a device pointer obtained at first call via kernel arg trick:
    // simplest: pass the symbol through a small setup — use cudaGetSymbolAddress (no alloc).
    if (!tmp_ptr) cudaGetSymbolAddress((void**)&tmp_ptr, g_tmp);

    cudaFuncSetAttribute(step_kernel, cudaFuncAttributeMaxDynamicSharedMemorySize, SMEM_STEP);
    cudaFuncSetAttribute(xgemm_kernel, cudaFuncAttributeMaxDynamicSharedMemorySize, 3 * BUFB);

    zero_state_kernel<<<(Bsz * Hdim + 255) / 256, 256>>>();
    split_w_kernel<<<(G4 * KTOT + 255) / 256, 256>>>(W_ih, W_hh);
    split_x_kernel<<<(Bsz * Slen * Fdim + 255) / 256, 256>>>(x);
    ctx1_kernel<<<Bsz, 128>>>(context, cg_w1, cg_b1, tmp_ptr);
    ctx2_kernel<<<Bsz, 256>>>(cg_w2, cg_b2);

    xgemm_kernel<<<dim3(32, 1024), 256, 3 * BUFB>>>();

    for (int t = 0; t < Slen; t++) {
        step_kernel<<<dim3(32, 8), 256, SMEM_STEP>>>(b_ih, b_hh, t);
    }

    head_kernel<<<Bsz, 128>>>(eps, mu_w, mu_b, lv_w, lv_b,
                              dec_w1, dec_b1, dec_w2, dec_b2, out);
}